// round 14
// baseline (speedup 1.0000x reference)
#include <cuda_runtime.h>

#define ADAM_B1 0.9f
#define ADAM_B2 0.999f
#define ADAM_LR 0.02f
#define LOG2E_F 1.4426950408889634f
#define LN2_F   0.6931471805599453f

__device__ __forceinline__ float rcp_a(float x) {
    float r; asm("rcp.approx.f32 %0, %1;" : "=f"(r) : "f"(x)); return r;
}
__device__ __forceinline__ float rsq_a(float x) {
    float r; asm("rsqrt.approx.f32 %0, %1;" : "=f"(r) : "f"(x)); return r;
}
__device__ __forceinline__ float sqrt_a(float x) {
    float r; asm("sqrt.approx.f32 %0, %1;" : "=f"(r) : "f"(x)); return r;
}
__device__ __forceinline__ float ex2_a(float x) {
    float r; asm("ex2.approx.f32 %0, %1;" : "=f"(r) : "f"(x)); return r;
}
#define EXPA(x) ex2_a(LOG2E_F * (x))

// ---------------- main kernel: 2 pixels per thread, PURE SCALAR ----------------
__global__ __launch_bounds__(32)
void pe_kernel(const float* __restrict__ X,     // (B,5,5)
               const float* __restrict__ Yg,    // (B,5)
               const float* __restrict__ ch0g,  // (B,1,3)
               const float* __restrict__ pf,    // (14,)
               const float* __restrict__ xag,   // (3,)
               const float* __restrict__ Sag,   // (3,3)
               const float* __restrict__ Seg,   // (5,5)
               const int*   __restrict__ nitp,
               float* __restrict__ out,         // (B,9)
               int B)
{
    int tIdx = blockIdx.x * blockDim.x + threadIdx.x;
    int p0i = 2 * tIdx;
    if (p0i >= B) return;
    int p1i = min(p0i + 1, B - 1);
    int px[2] = { p0i, p1i };

    const float L[5] = {-0.275f, 0.025f, 0.5f, 0.70f, 1.15f};

    // ---- uniform (broadcast) parameters ----
    float p0=pf[0], p1=pf[1], p2=pf[2], p3=pf[3], p4=pf[4], p5=pf[5], p6=pf[6],
          p7=pf[7], p8=pf[8], p9=pf[9], p10=pf[10], p11=pf[11], p12=pf[12], p13=pf[13];

    float AphS[5], AcdS[5], BbsS[5];
    #pragma unroll
    for (int l = 0; l < 5; l++) {
        AphS[l] = p0 * 0.05f * (1.0f + p1 * 0.1f * L[l] + p2 * 0.01f);
        AcdS[l] = p5 * 0.1f * expf(-p6 * 1.7f * L[l]);
        BbsS[l] = p3 * 0.001f * (1.0f + p4 * 0.05f * L[l]);
    }
    const float cna = p12 * 0.005f;
    const float cnb = p13 * 0.005f;
    const float c7s = p7 * 0.089f;
    const float c8s = p8 * 0.1245f;
    const float cnab = cna + cnb;

    // symmetrized matrices (uniform)
    float Se[5][5];
    #pragma unroll
    for (int i = 0; i < 5; i++)
        #pragma unroll
        for (int j = 0; j < 5; j++)
            Se[i][j] = 0.5f * (Seg[i*5 + j] + Seg[j*5 + i]);
    float SaS[3][3];
    #pragma unroll
    for (int i = 0; i < 3; i++)
        #pragma unroll
        for (int j = 0; j < 3; j++)
            SaS[i][j] = 0.5f * (Sag[i*3 + j] + Sag[j*3 + i]);
    float xa0 = xag[0], xa1 = xag[1], xa2 = xag[2];

    bool diag = (Se[0][1]==0.f && Se[0][2]==0.f && Se[0][3]==0.f && Se[0][4]==0.f &&
                 Se[1][2]==0.f && Se[1][3]==0.f && Se[1][4]==0.f &&
                 Se[2][3]==0.f && Se[2][4]==0.f && Se[3][4]==0.f &&
                 SaS[0][1]==0.f && SaS[0][2]==0.f && SaS[1][2]==0.f);

    // ---- per-pixel setup ----
    float fe[2][5], yv[2][5];
    #pragma unroll
    for (int s = 0; s < 2; s++) {
        int b = px[s];
        #pragma unroll
        for (int l = 0; l < 5; l++) {
            float e0 = X[b*25 + l*5 + 0], e1 = X[b*25 + l*5 + 1];
            fe[s][l] = __fdividef(e0 + 0.5f*e1, e0 + e1);
            yv[s][l] = Yg[b*5 + l];
        }
    }

    int iters = 50;
    if (nitp) {
        int it = *nitp;
        if (it >= 1 && it <= 100000000) iters = it;
        else {
            float f = __int_as_float(it);
            if (f >= 1.0f && f <= 1e8f) iters = (int)f;
        }
    }

    float b1t = 1.0f, b2t = 1.0f;
    float chOut[2][3];

    if (diag) {
        // ===== scalar fused diagonal path, log2-domain state, 2 independent chains =====
        float ABl[5], nABl[5], ACDl[5], nACDl[5], BBSl[5];
        #pragma unroll
        for (int l = 0; l < 5; l++) {
            ABl[l]   = AphS[l] + BbsS[l];
            nABl[l]  = -ABl[l];
            ACDl[l]  = AcdS[l];
            nACDl[l] = -AcdS[l];
            BBSl[l]  = BbsS[l];
        }
        const float sa0l2 = SaS[0][0]*LN2_F, sa1l2 = SaS[1][1]*LN2_F, sa2l2 = SaS[2][2]*LN2_F;
        const float bp0 = -SaS[0][0]*xa0, bp1 = -SaS[1][1]*xa1, bp2 = -SaS[2][2]*xa2;

        float fe2[2][5], yfn[2][5];
        #pragma unroll
        for (int s = 0; s < 2; s++) {
            int b = px[s];
            #pragma unroll
            for (int l = 0; l < 5; l++) {
                fe2[s][l] = Se[l][l] * fe[s][l] * fe[s][l];
                yfn[s][l] = -__fdividef(Yg[b*5 + l], fe[s][l]);
            }
        }

        // state: cl = ch*log2e, m, v — per pixel
        float cl[2][3], m[2][3], v[2][3];
        #pragma unroll
        for (int s = 0; s < 2; s++)
            #pragma unroll
            for (int k = 0; k < 3; k++) {
                cl[s][k] = ch0g[px[s]*3 + k] * LOG2E_F;
                m[s][k] = 0.0f;
                v[s][k] = 1e-30f;
            }

        for (int t = 0; t < iters; t++) {
            b1t *= ADAM_B1; b2t *= ADAM_B2;
            float nlrt = (-ADAM_LR * LOG2E_F) * sqrt_a(1.0f - b2t) * rcp_a(1.0f - b1t);

            #pragma unroll
            for (int s = 0; s < 2; s++) {
                float chla = ex2_a(cl[s][0]);
                float nap  = ex2_a(cl[s][1]);
                float cdom = ex2_a(cl[s][2]);

                float NC = fmaf(cnab, nap, 0.0057f);
                float DB = fmaf(cnb,  nap, 0.0012f);

                float acc0 = 0.f, S0 = 0.f, S1 = 0.f, acc2 = 0.f;
                #pragma unroll
                for (int l = 0; l < 5; l++) {
                    float sv = fmaf(ABl[l], chla, fmaf(ACDl[l], cdom, NC)); // a+bb
                    float bb = fmaf(BBSl[l], chla, DB);
                    float iv = rcp_a(sv);
                    float u  = bb * iv;
                    float t1 = fmaf(c8s, u, c7s);
                    float pv = fmaf(t1, u, yfn[s][l]);       // rrs/FE - Y/FE
                    float dv = fmaf(c8s, u, t1);             // c7 + 2 c8 u
                    float q  = (fe2[s][l] * iv) * (pv * dv);
                    float qu = q * u;
                    float tg = fmaf(u, nABl[l], BBSl[l]);    // BBS - u*(Aph+Bbs)
                    acc0 = fmaf(q, tg, acc0);
                    S0  += q;
                    S1  += qu;
                    acc2 = fmaf(qu, nACDl[l], acc2);         // -= qu*ACD
                }

                float g0 = fmaf(acc0, chla, fmaf(sa0l2, cl[s][0], bp0));
                float T  = fmaf(cnb, S0, -(cnab * S1));
                float g1 = fmaf(T, nap, fmaf(sa1l2, cl[s][1], bp1));
                float g2 = fmaf(acc2, cdom, fmaf(sa2l2, cl[s][2], bp2));

                float g[3] = { g0, g1, g2 };
                #pragma unroll
                for (int k = 0; k < 3; k++) {
                    m[s][k] = fmaf(g[k], 1.0f - ADAM_B1, m[s][k] * ADAM_B1);
                    v[s][k] = fmaf(g[k] * g[k], 1.0f - ADAM_B2, v[s][k] * ADAM_B2);
                    cl[s][k] = fmaf(m[s][k] * rsq_a(v[s][k]), nlrt, cl[s][k]);
                }
            }
        }
        #pragma unroll
        for (int s = 0; s < 2; s++)
            #pragma unroll
            for (int k = 0; k < 3; k++)
                chOut[s][k] = cl[s][k] * LN2_F;
    } else {
        // ===== general scalar two-pass fallback (dense Se, Sa) =====
        float bpf[3];
        bpf[0] = -(SaS[0][0]*xa0 + SaS[0][1]*xa1 + SaS[0][2]*xa2);
        bpf[1] = -(SaS[1][0]*xa0 + SaS[1][1]*xa1 + SaS[1][2]*xa2);
        bpf[2] = -(SaS[2][0]*xa0 + SaS[2][1]*xa1 + SaS[2][2]*xa2);

        float ch[2][3], m[2][3], v[2][3];
        #pragma unroll
        for (int s = 0; s < 2; s++)
            #pragma unroll
            for (int k = 0; k < 3; k++) {
                ch[s][k] = ch0g[px[s]*3 + k];
                m[s][k] = 0.0f;
                v[s][k] = 1e-30f;
            }

        for (int t = 0; t < iters; t++) {
            b1t *= ADAM_B1; b2t *= ADAM_B2;
            float nlrt = -ADAM_LR * sqrt_a(1.0f - b2t) * rcp_a(1.0f - b1t);

            #pragma unroll
            for (int s = 0; s < 2; s++) {
                float chla = EXPA(ch[s][0]);
                float nap  = EXPA(ch[s][1]);
                float cdom = EXPA(ch[s][2]);

                float da1  = cna * nap;
                float dbb1 = cnb * nap;

                float r[5], u[5], iv[5];
                #pragma unroll
                for (int l = 0; l < 5; l++) {
                    float a  = 0.0045f + AphS[l]*chla + AcdS[l]*cdom + da1;
                    float bb = 0.0012f + BbsS[l]*chla + dbb1;
                    iv[l] = rcp_a(a + bb);
                    u[l]  = bb * iv[l];
                    float rrs = fmaf(c8s, u[l], c7s) * u[l] * fe[s][l];
                    r[l] = rrs - yv[s][l];
                }

                float g0 = fmaf(SaS[0][0], ch[s][0], fmaf(SaS[0][1], ch[s][1], fmaf(SaS[0][2], ch[s][2], bpf[0])));
                float g1 = fmaf(SaS[1][0], ch[s][0], fmaf(SaS[1][1], ch[s][1], fmaf(SaS[1][2], ch[s][2], bpf[1])));
                float g2 = fmaf(SaS[2][0], ch[s][0], fmaf(SaS[2][1], ch[s][1], fmaf(SaS[2][2], ch[s][2], bpf[2])));

                #pragma unroll
                for (int l = 0; l < 5; l++) {
                    float w = fmaf(Se[l][0], r[0], fmaf(Se[l][1], r[1],
                              fmaf(Se[l][2], r[2], fmaf(Se[l][3], r[3], Se[l][4]*r[4]))));
                    float dg = fmaf(2.0f*c8s, u[l], c7s) * fe[s][l];
                    float q  = w * dg * iv[l];
                    float ul = u[l], om = 1.0f - ul;
                    float da0 = AphS[l]*chla, dbb0 = BbsS[l]*chla;
                    float da2 = AcdS[l]*cdom;
                    g0 += q * (om * dbb0 - ul * da0);
                    g1 += q * (om * dbb1 - ul * da1);
                    g2 -= q * ul * da2;
                }

                float g[3] = { g0, g1, g2 };
                #pragma unroll
                for (int k = 0; k < 3; k++) {
                    m[s][k] = fmaf(g[k], 1.0f - ADAM_B1, m[s][k] * ADAM_B1);
                    v[s][k] = fmaf(g[k] * g[k], 1.0f - ADAM_B2, v[s][k] * ADAM_B2);
                    ch[s][k] = fmaf(m[s][k] * rsq_a(v[s][k]), nlrt, ch[s][k]);
                }
            }
        }
        #pragma unroll
        for (int s = 0; s < 2; s++)
            #pragma unroll
            for (int k = 0; k < 3; k++)
                chOut[s][k] = ch[s][k];
    }

    // ---- outputs: [ch0, kd(5), bbp(3)] per pixel ----
    float kfac = p9 * 0.9f + p10 * 0.1f;

    #pragma unroll
    for (int s = 0; s < 2; s++) {
        int b = px[s];
        float chla = EXPA(chOut[s][0]);
        float nap  = EXPA(chOut[s][1]);
        float cdom = EXPA(chOut[s][2]);

        out[b*9 + 0] = chOut[s][0];
        #pragma unroll
        for (int l = 0; l < 5; l++) {
            float a  = 0.0045f + AphS[l]*chla + AcdS[l]*cdom + cna*nap;
            float bb = 0.0012f + BbsS[l]*chla + cnb*nap;
            float x3 = X[b*25 + l*5 + 3];
            float mu = 0.5f + 0.5f * rcp_a(1.0f + EXPA(-x3));
            out[b*9 + 1 + l] = (a + bb) * rcp_a(mu) * kfac;
        }
        const float L3[3] = {0.025f, 0.5f, 1.15f};
        #pragma unroll
        for (int j = 0; j < 3; j++) {
            out[b*9 + 6 + j] = p11 * (p3 * 0.001f * chla * (1.0f + p4 * 0.05f * L3[j]) + cnb * nap);
        }
    }
}

extern "C" void kernel_launch(void* const* d_in, const int* in_sizes, int n_in,
                              void* d_out, int out_size) {
    const float* X    = (const float*)d_in[0];
    const float* Y    = (const float*)d_in[1];
    const float* ch0  = (const float*)d_in[2];
    const float* pf   = (const float*)d_in[3];
    const float* xa   = (const float*)d_in[4];
    const float* Sa   = (const float*)d_in[5];
    const float* Se   = (const float*)d_in[6];
    const int*   nit  = (n_in >= 8) ? (const int*)d_in[7] : nullptr;
    float* out = (float*)d_out;

    int B = in_sizes[1] / 5;   // Y is (B,5)
    int nThreads = (B + 1) / 2;

    const int TPB = 32;
    int blocks = (nThreads + TPB - 1) / TPB;
    pe_kernel<<<blocks, TPB>>>(X, Y, ch0, pf, xa, Sa, Se, nit, out, B);
}